// round 11
// baseline (speedup 1.0000x reference)
#include <cuda_runtime.h>
#include <cuda_fp16.h>
#include <cstdint>

// y = conv2d(x[1,512,512,16], w[3,3,16,64], SAME); pot = y + old
// spike = pot >= 1; new_pot = spike ? 0 : pot
// d_out: [spikes 512*512*64][new_pot 512*512*64]
//
// HMMA implicit GEMM (mma.sync m16n8k16 f16, f32 acc), split-2 fp16 emulation.
// Block tile: 128 px x 64 cout x 4 y-rows. Warp: 32 px x 32 couts per row.
// A rows live in a 4-slot ring; next source row prefetched raw via cp.async
// during the current row's mainloop. 2 CTAs/SM.

#define HH 512
#define WW 512
#define CIN 16
#define COUT 64
#define TH 4

#define B_BYTES (9 * 2 * 8 * 32 * 8)   /* 36864 */
#define A_PITCH 48                     /* bytes per px-row (16B-mult, ldmatrix ok) */
#define A_SLOT  (130 * A_PITCH)        /* 6240 per (split,slot) */
#define A_OFF   B_BYTES
#define LO_OFF  (4 * A_SLOT)           /* lo split bank of the ring */
#define RAW_OFF (A_OFF + 8 * A_SLOT)   /* raw fp32 prefetch buffer */
#define RAW_BYTES (130 * 64)           /* 8320 */
#define SMEM_TOTAL (RAW_OFF + RAW_BYTES) /* 95104 ; x2 = 190208 <= 228KB */

__device__ static uint2 g_Bfrag[9 * 2 * 8 * 32];

__device__ __forceinline__ uint32_t smem_u32(const void* p) {
    uint32_t a;
    asm("{ .reg .u64 t; cvta.to.shared.u64 t, %1; cvt.u32.u64 %0, t; }"
        : "=r"(a) : "l"(p));
    return a;
}
__device__ __forceinline__ uint32_t pack_h2(float a, float b) {
    __half2 h = __floats2half2_rn(a, b);
    return *(uint32_t*)&h;
}
__device__ __forceinline__ float h_rt(float v) {
    return __half2float(__float2half_rn(v));
}
__device__ __forceinline__ void ldmatrix_x4(uint32_t* r, uint32_t addr) {
    asm volatile("ldmatrix.sync.aligned.m8n8.x4.shared.b16 {%0,%1,%2,%3}, [%4];"
                 : "=r"(r[0]), "=r"(r[1]), "=r"(r[2]), "=r"(r[3]) : "r"(addr));
}
__device__ __forceinline__ void mma_f16(float* d, const uint32_t* a, uint2 b) {
    asm volatile(
        "mma.sync.aligned.m16n8k16.row.col.f32.f16.f16.f32 "
        "{%0,%1,%2,%3}, {%4,%5,%6,%7}, {%8,%9}, {%0,%1,%2,%3};"
        : "+f"(d[0]), "+f"(d[1]), "+f"(d[2]), "+f"(d[3])
        : "r"(a[0]), "r"(a[1]), "r"(a[2]), "r"(a[3]), "r"(b.x), "r"(b.y));
}
__device__ __forceinline__ void cp_async16(uint32_t dst, const void* src) {
    asm volatile("cp.async.cg.shared.global [%0], [%1], 16;"
                 :: "r"(dst), "l"(src) : "memory");
}

// ---- prep: build B fragments (hi/lo) in m16n8k16 .col lane layout ----
__global__ void prep_weights(const float* __restrict__ wt) {
    int idx = blockIdx.x * 256 + threadIdx.x;
    if (idx >= 9 * 2 * 8 * 32) return;
    int lane = idx & 31;
    int t = idx >> 5;
    int nt = t & 7;  t >>= 3;
    int s = t & 1;
    int tap = t >> 1;
    int g = lane >> 2, tg = lane & 3;
    int n = nt * 8 + g;
    float w[4];
    int kk[4] = {tg * 2, tg * 2 + 1, tg * 2 + 8, tg * 2 + 9};
    #pragma unroll
    for (int j = 0; j < 4; j++) {
        float wv = wt[(tap * 16 + kk[j]) * 64 + n];
        w[j] = s == 0 ? wv : (wv - h_rt(wv));
    }
    g_Bfrag[idx] = make_uint2(pack_h2(w[0], w[1]), pack_h2(w[2], w[3]));
}

// split 4 ci values of pixel-row p into ring slot
__device__ __forceinline__ void write_split(char* smem, int slot, int p, int q,
                                            float4 v) {
    float hx = h_rt(v.x), hy = h_rt(v.y);
    float hz = h_rt(v.z), hw = h_rt(v.w);
    char* rh = smem + A_OFF + slot * A_SLOT + p * A_PITCH + q * 8;
    char* rl = rh + LO_OFF;
    *(uint32_t*)(rh)     = pack_h2(v.x, v.y);
    *(uint32_t*)(rh + 4) = pack_h2(v.z, v.w);
    *(uint32_t*)(rl)     = pack_h2(v.x - hx, v.y - hy);
    *(uint32_t*)(rl + 4) = pack_h2(v.z - hz, v.w - hw);
}

// ---- main kernel ----
__global__ void __launch_bounds__(256, 2)
snn_conv_mma(const float* __restrict__ in, const float* __restrict__ oldp,
             float* __restrict__ out_spk, float* __restrict__ out_pot) {
    extern __shared__ char smem[];
    const uint32_t sb = smem_u32(smem);
    const int tid = threadIdx.x;
    const int wid = tid >> 5;
    const int lane = tid & 31;
    const int x0 = blockIdx.x * 128;
    const int y0 = blockIdx.y * TH;

    // ---- prologue: B via cp.async; slots 0..2 staged directly ----
    #pragma unroll
    for (int i = tid; i < B_BYTES / 16; i += 256)
        cp_async16(sb + i * 16, (const char*)g_Bfrag + i * 16);

    for (int i = tid; i < 3 * 130 * 4; i += 256) {
        int q = i & 3;
        int t = i >> 2;
        int p = t % 130;
        int r = t / 130;                 // source row index 0..2 -> slot r
        int gx = x0 + p - 1, gy = y0 + r - 1;
        float4 v = make_float4(0.f, 0.f, 0.f, 0.f);
        if ((unsigned)gx < WW && (unsigned)gy < HH)
            v = *(const float4*)(in + (gy * WW + gx) * CIN + q * 4);
        write_split(smem, r, p, q, v);
    }
    // prefetch source row 3 raw
    {
        int gy = y0 + 2;                 // src row 3 => gy = y0 + 3 - 1
        for (int i = tid; i < 130 * 4; i += 256) {
            int q = i & 3, p = i >> 2;
            int gx = x0 + p - 1;
            uint32_t dst = sb + RAW_OFF + p * 64 + q * 16;
            if ((unsigned)gx < WW && (unsigned)gy < HH)
                cp_async16(dst, in + (gy * WW + gx) * CIN + q * 4);
            else
                asm volatile("st.shared.v4.b32 [%0], {%1,%1,%1,%1};"
                             :: "r"(dst), "r"(0) : "memory");
        }
    }
    asm volatile("cp.async.wait_all;" ::: "memory");
    __syncthreads();

    // warp tile: pixels m0..m0+31, couts cb..cb+31
    const int m0 = (wid >> 1) * 32;
    const int cb = (wid & 1) * 32;
    const uint32_t rowsel = (lane & 7) + ((lane >> 3) & 1) * 8;
    const uint32_t koff = (lane >> 4) * 16;
    const int g = lane >> 2, tg = lane & 3;

    #pragma unroll 1
    for (int r = 0; r < TH; r++) {
        float acc[2][4][4];
        #pragma unroll
        for (int t = 0; t < 2; t++)
            #pragma unroll
            for (int nt = 0; nt < 4; nt++)
                #pragma unroll
                for (int j = 0; j < 4; j++) acc[t][nt][j] = 0.f;

        // ---- mainloop for output row y0 + r ----
        #pragma unroll
        for (int tap = 0; tap < 9; tap++) {
            const int dy = tap / 3, dx = tap - dy * 3;
            const char* bb = smem + (tap * 2 * 8 * 32 + lane) * 8 + (cb / 8) * 256;
            uint2 bh[4], bl[4];
            #pragma unroll
            for (int nt = 0; nt < 4; nt++) {
                bh[nt] = *(const uint2*)(bb + nt * 256);
                bl[nt] = *(const uint2*)(bb + nt * 256 + 2048);
            }
            int slot = (r + dy) & 3;
            uint32_t abase = sb + A_OFF + slot * A_SLOT +
                             (m0 + dx + rowsel) * A_PITCH + koff;
            #pragma unroll
            for (int t = 0; t < 2; t++) {
                uint32_t ah[4], al[4];
                uint32_t aaddr = abase + t * (16 * A_PITCH);
                ldmatrix_x4(ah, aaddr);
                ldmatrix_x4(al, aaddr + LO_OFF);
                #pragma unroll
                for (int nt = 0; nt < 4; nt++) mma_f16(acc[t][nt], ah, bh[nt]);
                #pragma unroll
                for (int nt = 0; nt < 4; nt++) mma_f16(acc[t][nt], ah, bl[nt]);
                #pragma unroll
                for (int nt = 0; nt < 4; nt++) mma_f16(acc[t][nt], al, bh[nt]);
            }
        }

        // ---- epilogue for this row ----
        #pragma unroll
        for (int t = 0; t < 2; t++) {
            #pragma unroll
            for (int half = 0; half < 2; half++) {
                int m = m0 + t * 16 + half * 8 + g;
                int base = ((y0 + r) * WW + x0 + m) * COUT + cb + tg * 2;
                #pragma unroll
                for (int nt = 0; nt < 4; nt++) {
                    int off = base + nt * 8;
                    float2 o = __ldcs((const float2*)(oldp + off));
                    float v0 = acc[t][nt][half * 2 + 0] + o.x;
                    float v1 = acc[t][nt][half * 2 + 1] + o.y;
                    bool f0 = v0 >= 1.f, f1 = v1 >= 1.f;
                    __stcs((float2*)(out_spk + off),
                           make_float2(f0 ? 1.f : 0.f, f1 ? 1.f : 0.f));
                    __stcs((float2*)(out_pot + off),
                           make_float2(f0 ? 0.f : v0, f1 ? 0.f : v1));
                }
            }
        }

        // ---- rotate ring: convert prefetched raw row -> slot (r+3)&3 ----
        if (r < TH - 1) {
            asm volatile("cp.async.wait_all;" ::: "memory");
            __syncthreads();           // mainloop(r) done; raw visible
            int slot = (r + 3) & 3;
            for (int i = tid; i < 130 * 4; i += 256) {
                int q = i & 3, p = i >> 2;
                float4 v = *(const float4*)(smem + RAW_OFF + p * 64 + q * 16);
                write_split(smem, slot, p, q, v);
            }
            __syncthreads();           // split visible; raw reads done
            if (r < TH - 2) {          // prefetch next raw row
                int gy = y0 + r + 3;   // src row r+4 => gy = y0 + r + 4 - 1
                for (int i = tid; i < 130 * 4; i += 256) {
                    int q = i & 3, p = i >> 2;
                    int gx = x0 + p - 1;
                    uint32_t dst = sb + RAW_OFF + p * 64 + q * 16;
                    if ((unsigned)gx < WW && (unsigned)gy < HH)
                        cp_async16(dst, in + (gy * WW + gx) * CIN + q * 4);
                    else
                        asm volatile("st.shared.v4.b32 [%0], {%1,%1,%1,%1};"
                                     :: "r"(dst), "r"(0) : "memory");
                }
            }
        }
    }
}

extern "C" void kernel_launch(void* const* d_in, const int* in_sizes, int n_in,
                              void* d_out, int out_size) {
    const float* in   = (const float*)d_in[0];   // [1,512,512,16]
    const float* wt   = (const float*)d_in[1];   // [3,3,16,64]
    const float* oldp = (const float*)d_in[2];   // [1,512,512,64]
    float* spk = (float*)d_out;
    float* pot = (float*)d_out + in_sizes[2];

    prep_weights<<<(9 * 2 * 8 * 32 + 255) / 256, 256>>>(wt);

    cudaFuncSetAttribute(snn_conv_mma,
                         cudaFuncAttributeMaxDynamicSharedMemorySize, SMEM_TOTAL);
    dim3 grid(WW / 128, HH / TH);   // 4 x 128 = 512 blocks
    snn_conv_mma<<<grid, 256, SMEM_TOTAL>>>(in, oldp, spk, pot);
}

// round 12
// speedup vs baseline: 1.1634x; 1.1634x over previous
#include <cuda_runtime.h>
#include <cuda_fp16.h>
#include <cstdint>

// y = conv2d(x[1,512,512,16], w[3,3,16,64], SAME); pot = y + old
// spike = pot >= 1; new_pot = spike ? 0 : pot
// d_out: [spikes 512*512*64][new_pot 512*512*64]
//
// HMMA implicit GEMM (mma.sync m16n8k16 f16, f32 acc), split-2 fp16 emulation.
// Warp tile 32 px x 32 couts; block = 128 px x 64 couts; 3 CTAs/SM.
// R12: B table permuted for LDS.128; MMA chains interleaved across px-halves
// (dependent MMAs 8 apart); al ldmatrix deferred.

#define HH 512
#define WW 512
#define CIN 16
#define COUT 64

#define B_BYTES (9 * 2 * 2 * 2 * 32 * 16) /* 36864 */
#define A_PITCH 48                     /* bytes per pixel-row: 16 ci f16 + pad */
#define A_BUF   (130 * A_PITCH)        /* 6240 per (split,row) buffer */
#define A_OFF   B_BYTES
#define SMEM_TOTAL (A_OFF + 6 * A_BUF) /* 74304 ; x3 CTAs = 222912 <= 228KB */

// B fragments: [tap][cbhalf][split][ntpair][lane]{16B = 2 frags}
__device__ static uint2 g_Bfrag[9 * 2 * 2 * 2 * 32 * 2];

__device__ __forceinline__ uint32_t smem_u32(const void* p) {
    uint32_t a;
    asm("{ .reg .u64 t; cvta.to.shared.u64 t, %1; cvt.u32.u64 %0, t; }"
        : "=r"(a) : "l"(p));
    return a;
}
__device__ __forceinline__ uint32_t pack_h2(float a, float b) {
    __half2 h = __floats2half2_rn(a, b);
    return *(uint32_t*)&h;
}
__device__ __forceinline__ float h_rt(float v) {
    return __half2float(__float2half_rn(v));
}
__device__ __forceinline__ void ldmatrix_x4(uint32_t* r, uint32_t addr) {
    asm volatile("ldmatrix.sync.aligned.m8n8.x4.shared.b16 {%0,%1,%2,%3}, [%4];"
                 : "=r"(r[0]), "=r"(r[1]), "=r"(r[2]), "=r"(r[3]) : "r"(addr));
}
__device__ __forceinline__ void mma_f16(float* d, const uint32_t* a, uint2 b) {
    asm volatile(
        "mma.sync.aligned.m16n8k16.row.col.f32.f16.f16.f32 "
        "{%0,%1,%2,%3}, {%4,%5,%6,%7}, {%8,%9}, {%0,%1,%2,%3};"
        : "+f"(d[0]), "+f"(d[1]), "+f"(d[2]), "+f"(d[3])
        : "r"(a[0]), "r"(a[1]), "r"(a[2]), "r"(a[3]), "r"(b.x), "r"(b.y));
}
__device__ __forceinline__ void cp_async16(uint32_t dst, const void* src) {
    asm volatile("cp.async.cg.shared.global [%0], [%1], 16;"
                 :: "r"(dst), "l"(src) : "memory");
}

// ---- prep: B fragments (hi/lo) in m16n8k16 .col layout, LDS.128-friendly ----
__global__ void prep_weights(const float* __restrict__ wt) {
    int idx = blockIdx.x * 256 + threadIdx.x;   // one uint2 each; 4608 total
    if (idx >= 9 * 2 * 2 * 2 * 32 * 2) return;
    int ni   = idx & 1;
    int lane = (idx >> 1) & 31;
    int np   = (idx >> 6) & 1;
    int s    = (idx >> 7) & 1;
    int cbh  = (idx >> 8) & 1;
    int tap  = idx >> 9;
    int nt = cbh * 4 + np * 2 + ni;       // global n-tile 0..7
    int g = lane >> 2, tg = lane & 3;
    int n = nt * 8 + g;
    float w[4];
    int kk[4] = {tg * 2, tg * 2 + 1, tg * 2 + 8, tg * 2 + 9};
    #pragma unroll
    for (int j = 0; j < 4; j++) {
        float wv = wt[(tap * 16 + kk[j]) * 64 + n];
        w[j] = s == 0 ? wv : (wv - h_rt(wv));
    }
    g_Bfrag[idx] = make_uint2(pack_h2(w[0], w[1]), pack_h2(w[2], w[3]));
}

// ---- main kernel ----
__global__ void __launch_bounds__(256, 3)
snn_conv_mma(const float* __restrict__ in, const float* __restrict__ oldp,
             float* __restrict__ out_spk, float* __restrict__ out_pot) {
    extern __shared__ char smem[];
    const uint32_t sb = smem_u32(smem);
    const int tid = threadIdx.x;
    const int wid = tid >> 5;
    const int lane = tid & 31;
    const int x0 = blockIdx.x * 128;
    const int y  = blockIdx.y;

    // ---- stage B fragments via cp.async ----
    #pragma unroll
    for (int i = tid; i < B_BYTES / 16; i += 256)
        cp_async16(sb + i * 16, (const char*)g_Bfrag + i * 16);
    asm volatile("cp.async.commit_group;" ::: "memory");

    // ---- stage A: 3 source rows x 130 px x 16 ci, split hi/lo fp16 ----
    for (int i = tid; i < 3 * 130 * 4; i += 256) {
        int q = i & 3;
        int t = i >> 2;
        int p = t % 130;          // buffer row (gx = x0 + p - 1)
        int r = t / 130;          // source row (gy = y + r - 1)
        int gx = x0 + p - 1, gy = y + r - 1;
        float4 v = make_float4(0.f, 0.f, 0.f, 0.f);
        if ((unsigned)gx < WW && (unsigned)gy < HH)
            v = *(const float4*)(in + (gy * WW + gx) * CIN + q * 4);
        float hx = h_rt(v.x), hy = h_rt(v.y);
        float hz = h_rt(v.z), hw = h_rt(v.w);
        char* rh = smem + A_OFF + r * A_BUF + p * A_PITCH + q * 8;
        char* rl = rh + 3 * A_BUF;
        *(uint32_t*)(rh)     = pack_h2(v.x, v.y);
        *(uint32_t*)(rh + 4) = pack_h2(v.z, v.w);
        *(uint32_t*)(rl)     = pack_h2(v.x - hx, v.y - hy);
        *(uint32_t*)(rl + 4) = pack_h2(v.z - hz, v.w - hw);
    }
    asm volatile("cp.async.wait_all;" ::: "memory");
    __syncthreads();

    // warp tile: pixels m0..m0+31, couts cb..cb+31
    const int m0 = (wid >> 1) * 32;
    const int cbh = wid & 1;
    const uint32_t rowsel = (lane & 7) + ((lane >> 3) & 1) * 8;
    const uint32_t koff = (lane >> 4) * 16;

    float acc[2][4][4];    // [px-half][n-tile][frag]
    #pragma unroll
    for (int t = 0; t < 2; t++)
        #pragma unroll
        for (int nt = 0; nt < 4; nt++)
            #pragma unroll
            for (int j = 0; j < 4; j++) acc[t][nt][j] = 0.f;

    #pragma unroll
    for (int tap = 0; tap < 9; tap++) {
        const int dy = tap / 3, dx = tap - dy * 3;
        // B: 4 x LDS.128 (this warp's cout half; hi then lo)
        const char* bb = smem + (tap * 2 + cbh) * 2048 + lane * 16;
        uint4 h01 = *(const uint4*)(bb);
        uint4 h23 = *(const uint4*)(bb + 512);
        uint2 bh[4] = {make_uint2(h01.x, h01.y), make_uint2(h01.z, h01.w),
                       make_uint2(h23.x, h23.y), make_uint2(h23.z, h23.w)};

        uint32_t abase = sb + A_OFF + dy * A_BUF +
                         (m0 + dx + rowsel) * A_PITCH + koff;
        uint32_t ah0[4], ah1[4];
        ldmatrix_x4(ah0, abase);
        ldmatrix_x4(ah1, abase + 16 * A_PITCH);

        // hh products: 8 independent chains
        #pragma unroll
        for (int nt = 0; nt < 4; nt++) mma_f16(acc[0][nt], ah0, bh[nt]);
        #pragma unroll
        for (int nt = 0; nt < 4; nt++) mma_f16(acc[1][nt], ah1, bh[nt]);

        uint4 l01 = *(const uint4*)(bb + 1024);
        uint4 l23 = *(const uint4*)(bb + 1536);
        uint2 bl[4] = {make_uint2(l01.x, l01.y), make_uint2(l01.z, l01.w),
                       make_uint2(l23.x, l23.y), make_uint2(l23.z, l23.w)};

        // hi * lo_w
        #pragma unroll
        for (int nt = 0; nt < 4; nt++) mma_f16(acc[0][nt], ah0, bl[nt]);
        #pragma unroll
        for (int nt = 0; nt < 4; nt++) mma_f16(acc[1][nt], ah1, bl[nt]);

        uint32_t al0[4], al1[4];
        ldmatrix_x4(al0, abase + 3 * A_BUF);
        ldmatrix_x4(al1, abase + 3 * A_BUF + 16 * A_PITCH);

        // lo_x * hi
        #pragma unroll
        for (int nt = 0; nt < 4; nt++) mma_f16(acc[0][nt], al0, bh[nt]);
        #pragma unroll
        for (int nt = 0; nt < 4; nt++) mma_f16(acc[1][nt], al1, bh[nt]);
    }

    // ---- epilogue: +old, threshold, reset, streaming stores ----
    const int g = lane >> 2, tg = lane & 3;
    const int cb = cbh * 32;
    #pragma unroll
    for (int t = 0; t < 2; t++) {
        #pragma unroll
        for (int half = 0; half < 2; half++) {
            int m = m0 + t * 16 + half * 8 + g;
            int base = (y * WW + x0 + m) * COUT + cb + tg * 2;
            #pragma unroll
            for (int nt = 0; nt < 4; nt++) {
                int off = base + nt * 8;
                float2 o = __ldcs((const float2*)(oldp + off));
                float v0 = acc[t][nt][half * 2 + 0] + o.x;
                float v1 = acc[t][nt][half * 2 + 1] + o.y;
                bool f0 = v0 >= 1.f, f1 = v1 >= 1.f;
                __stcs((float2*)(out_spk + off),
                       make_float2(f0 ? 1.f : 0.f, f1 ? 1.f : 0.f));
                __stcs((float2*)(out_pot + off),
                       make_float2(f0 ? 0.f : v0, f1 ? 0.f : v1));
            }
        }
    }
}

extern "C" void kernel_launch(void* const* d_in, const int* in_sizes, int n_in,
                              void* d_out, int out_size) {
    const float* in   = (const float*)d_in[0];   // [1,512,512,16]
    const float* wt   = (const float*)d_in[1];   // [3,3,16,64]
    const float* oldp = (const float*)d_in[2];   // [1,512,512,64]
    float* spk = (float*)d_out;
    float* pot = (float*)d_out + in_sizes[2];

    prep_weights<<<(9 * 2 * 2 * 2 * 32 * 2 + 255) / 256, 256>>>(wt);

    cudaFuncSetAttribute(snn_conv_mma,
                         cudaFuncAttributeMaxDynamicSharedMemorySize, SMEM_TOTAL);
    dim3 grid(WW / 128, HH);   // 4 x 512
    snn_conv_mma<<<grid, 256, SMEM_TOTAL>>>(in, oldp, spk, pot);
}

// round 13
// speedup vs baseline: 1.3053x; 1.1219x over previous
#include <cuda_runtime.h>
#include <cuda_fp16.h>
#include <cstdint>

// y = conv2d(x[1,512,512,16], w[3,3,16,64], SAME); pot = y + old
// spike = pot >= 1; new_pot = spike ? 0 : pot
// d_out: [spikes 512*512*64][new_pot 512*512*64]
//
// HMMA implicit GEMM (mma.sync m16n8k16 f16, f32 acc), split-2 fp16 emulation.
// Warp tile 32 px x 32 couts; block = 128 px x 64 couts; 3 CTAs/SM (RF-capped).
// R13: R10 ordering (ALL tap loads before MMAs) + B as 4x LDS.128 upfront +
// batched epilogue loads.

#define HH 512
#define WW 512
#define CIN 16
#define COUT 64

#define B_BYTES (9 * 2 * 2 * 2 * 32 * 16) /* 36864 */
#define A_PITCH 48                     /* bytes per pixel-row: 16 ci f16 + pad */
#define A_BUF   (130 * A_PITCH)        /* 6240 per (split,row) buffer */
#define A_OFF   B_BYTES
#define SMEM_TOTAL (A_OFF + 6 * A_BUF) /* 74304 ; x3 CTAs = 222912 <= 228KB */

// B fragments: [tap][cbhalf][split][ntpair][lane]{16B = 2 frags}
__device__ static uint2 g_Bfrag[9 * 2 * 2 * 2 * 32 * 2];

__device__ __forceinline__ uint32_t smem_u32(const void* p) {
    uint32_t a;
    asm("{ .reg .u64 t; cvta.to.shared.u64 t, %1; cvt.u32.u64 %0, t; }"
        : "=r"(a) : "l"(p));
    return a;
}
__device__ __forceinline__ uint32_t pack_h2(float a, float b) {
    __half2 h = __floats2half2_rn(a, b);
    return *(uint32_t*)&h;
}
__device__ __forceinline__ float h_rt(float v) {
    return __half2float(__float2half_rn(v));
}
__device__ __forceinline__ void ldmatrix_x4(uint32_t* r, uint32_t addr) {
    asm volatile("ldmatrix.sync.aligned.m8n8.x4.shared.b16 {%0,%1,%2,%3}, [%4];"
                 : "=r"(r[0]), "=r"(r[1]), "=r"(r[2]), "=r"(r[3]) : "r"(addr));
}
__device__ __forceinline__ void mma_f16(float* d, const uint32_t* a, uint2 b) {
    asm volatile(
        "mma.sync.aligned.m16n8k16.row.col.f32.f16.f16.f32 "
        "{%0,%1,%2,%3}, {%4,%5,%6,%7}, {%8,%9}, {%0,%1,%2,%3};"
        : "+f"(d[0]), "+f"(d[1]), "+f"(d[2]), "+f"(d[3])
        : "r"(a[0]), "r"(a[1]), "r"(a[2]), "r"(a[3]), "r"(b.x), "r"(b.y));
}
__device__ __forceinline__ void cp_async16(uint32_t dst, const void* src) {
    asm volatile("cp.async.cg.shared.global [%0], [%1], 16;"
                 :: "r"(dst), "l"(src) : "memory");
}

// ---- prep: B fragments (hi/lo) in m16n8k16 .col layout, LDS.128-friendly ----
__global__ void prep_weights(const float* __restrict__ wt) {
    int idx = blockIdx.x * 256 + threadIdx.x;   // one uint2 each; 4608 total
    if (idx >= 9 * 2 * 2 * 2 * 32 * 2) return;
    int ni   = idx & 1;
    int lane = (idx >> 1) & 31;
    int np   = (idx >> 6) & 1;
    int s    = (idx >> 7) & 1;
    int cbh  = (idx >> 8) & 1;
    int tap  = idx >> 9;
    int nt = cbh * 4 + np * 2 + ni;       // global n-tile 0..7
    int g = lane >> 2, tg = lane & 3;
    int n = nt * 8 + g;
    float w[4];
    int kk[4] = {tg * 2, tg * 2 + 1, tg * 2 + 8, tg * 2 + 9};
    #pragma unroll
    for (int j = 0; j < 4; j++) {
        float wv = wt[(tap * 16 + kk[j]) * 64 + n];
        w[j] = s == 0 ? wv : (wv - h_rt(wv));
    }
    g_Bfrag[idx] = make_uint2(pack_h2(w[0], w[1]), pack_h2(w[2], w[3]));
}

// ---- main kernel ----
__global__ void __launch_bounds__(256, 3)
snn_conv_mma(const float* __restrict__ in, const float* __restrict__ oldp,
             float* __restrict__ out_spk, float* __restrict__ out_pot) {
    extern __shared__ char smem[];
    const uint32_t sb = smem_u32(smem);
    const int tid = threadIdx.x;
    const int wid = tid >> 5;
    const int lane = tid & 31;
    const int x0 = blockIdx.x * 128;
    const int y  = blockIdx.y;

    // ---- stage B fragments via cp.async ----
    #pragma unroll
    for (int i = tid; i < B_BYTES / 16; i += 256)
        cp_async16(sb + i * 16, (const char*)g_Bfrag + i * 16);
    asm volatile("cp.async.commit_group;" ::: "memory");

    // ---- stage A: 3 source rows x 130 px x 16 ci, split hi/lo fp16 ----
    for (int i = tid; i < 3 * 130 * 4; i += 256) {
        int q = i & 3;
        int t = i >> 2;
        int p = t % 130;          // buffer row (gx = x0 + p - 1)
        int r = t / 130;          // source row (gy = y + r - 1)
        int gx = x0 + p - 1, gy = y + r - 1;
        float4 v = make_float4(0.f, 0.f, 0.f, 0.f);
        if ((unsigned)gx < WW && (unsigned)gy < HH)
            v = *(const float4*)(in + (gy * WW + gx) * CIN + q * 4);
        float hx = h_rt(v.x), hy = h_rt(v.y);
        float hz = h_rt(v.z), hw = h_rt(v.w);
        char* rh = smem + A_OFF + r * A_BUF + p * A_PITCH + q * 8;
        char* rl = rh + 3 * A_BUF;
        *(uint32_t*)(rh)     = pack_h2(v.x, v.y);
        *(uint32_t*)(rh + 4) = pack_h2(v.z, v.w);
        *(uint32_t*)(rl)     = pack_h2(v.x - hx, v.y - hy);
        *(uint32_t*)(rl + 4) = pack_h2(v.z - hz, v.w - hw);
    }
    asm volatile("cp.async.wait_all;" ::: "memory");
    __syncthreads();

    // warp tile: pixels m0..m0+31, couts cb..cb+31
    const int m0 = (wid >> 1) * 32;
    const int cbh = wid & 1;
    const uint32_t rowsel = (lane & 7) + ((lane >> 3) & 1) * 8;
    const uint32_t koff = (lane >> 4) * 16;

    float acc[2][4][4];    // [px-half][n-tile][frag]
    #pragma unroll
    for (int t = 0; t < 2; t++)
        #pragma unroll
        for (int nt = 0; nt < 4; nt++)
            #pragma unroll
            for (int j = 0; j < 4; j++) acc[t][nt][j] = 0.f;

    #pragma unroll
    for (int tap = 0; tap < 9; tap++) {
        const int dy = tap / 3, dx = tap - dy * 3;
        // ALL loads of this tap first (load-upfront: max MLP, R10 discipline)
        const char* bb = smem + (tap * 2 + cbh) * 2048 + lane * 16;
        uint4 h01 = *(const uint4*)(bb);
        uint4 h23 = *(const uint4*)(bb + 512);
        uint4 l01 = *(const uint4*)(bb + 1024);
        uint4 l23 = *(const uint4*)(bb + 1536);

        uint32_t abase = sb + A_OFF + dy * A_BUF +
                         (m0 + dx + rowsel) * A_PITCH + koff;
        uint32_t ah0[4], ah1[4], al0[4], al1[4];
        ldmatrix_x4(ah0, abase);
        ldmatrix_x4(al0, abase + 3 * A_BUF);
        ldmatrix_x4(ah1, abase + 16 * A_PITCH);
        ldmatrix_x4(al1, abase + 3 * A_BUF + 16 * A_PITCH);

        uint2 bh[4] = {make_uint2(h01.x, h01.y), make_uint2(h01.z, h01.w),
                       make_uint2(h23.x, h23.y), make_uint2(h23.z, h23.w)};
        uint2 bl[4] = {make_uint2(l01.x, l01.y), make_uint2(l01.z, l01.w),
                       make_uint2(l23.x, l23.y), make_uint2(l23.z, l23.w)};

        // R10 MMA order: per px-half, product-major groups of 4
        #pragma unroll
        for (int nt = 0; nt < 4; nt++) mma_f16(acc[0][nt], ah0, bh[nt]);
        #pragma unroll
        for (int nt = 0; nt < 4; nt++) mma_f16(acc[0][nt], ah0, bl[nt]);
        #pragma unroll
        for (int nt = 0; nt < 4; nt++) mma_f16(acc[0][nt], al0, bh[nt]);
        #pragma unroll
        for (int nt = 0; nt < 4; nt++) mma_f16(acc[1][nt], ah1, bh[nt]);
        #pragma unroll
        for (int nt = 0; nt < 4; nt++) mma_f16(acc[1][nt], ah1, bl[nt]);
        #pragma unroll
        for (int nt = 0; nt < 4; nt++) mma_f16(acc[1][nt], al1, bh[nt]);
    }

    // ---- epilogue: batched loads per px-half, threshold, streaming stores ----
    const int g = lane >> 2, tg = lane & 3;
    const int cb = cbh * 32;
    #pragma unroll
    for (int t = 0; t < 2; t++) {
        int base0 = (y * WW + x0 + m0 + t * 16 + g) * COUT + cb + tg * 2;
        int base1 = base0 + 8 * COUT;   // second 8-row half
        float2 o[8];
        #pragma unroll
        for (int nt = 0; nt < 4; nt++) {
            o[nt]     = __ldcs((const float2*)(oldp + base0 + nt * 8));
            o[nt + 4] = __ldcs((const float2*)(oldp + base1 + nt * 8));
        }
        #pragma unroll
        for (int half = 0; half < 2; half++) {
            int base = half ? base1 : base0;
            #pragma unroll
            for (int nt = 0; nt < 4; nt++) {
                float2 ov = o[half * 4 + nt];
                float v0 = acc[t][nt][half * 2 + 0] + ov.x;
                float v1 = acc[t][nt][half * 2 + 1] + ov.y;
                bool f0 = v0 >= 1.f, f1 = v1 >= 1.f;
                __stcs((float2*)(out_spk + base + nt * 8),
                       make_float2(f0 ? 1.f : 0.f, f1 ? 1.f : 0.f));
                __stcs((float2*)(out_pot + base + nt * 8),
                       make_float2(f0 ? 0.f : v0, f1 ? 0.f : v1));
            }
        }
    }
}

extern "C" void kernel_launch(void* const* d_in, const int* in_sizes, int n_in,
                              void* d_out, int out_size) {
    const float* in   = (const float*)d_in[0];   // [1,512,512,16]
    const float* wt   = (const float*)d_in[1];   // [3,3,16,64]
    const float* oldp = (const float*)d_in[2];   // [1,512,512,64]
    float* spk = (float*)d_out;
    float* pot = (float*)d_out + in_sizes[2];

    prep_weights<<<(9 * 2 * 2 * 2 * 32 * 2 + 255) / 256, 256>>>(wt);

    cudaFuncSetAttribute(snn_conv_mma,
                         cudaFuncAttributeMaxDynamicSharedMemorySize, SMEM_TOTAL);
    dim3 grid(WW / 128, HH);   // 4 x 512
    snn_conv_mma<<<grid, 256, SMEM_TOTAL>>>(in, oldp, spk, pot);
}

// round 14
// speedup vs baseline: 1.3762x; 1.0543x over previous
#include <cuda_runtime.h>
#include <cuda_fp16.h>
#include <cstdint>

// y = conv2d(x[1,512,512,16], w[3,3,16,64], SAME); pot = y + old
// spike = pot >= 1; new_pot = spike ? 0 : pot
// d_out: [spikes 512*512*64][new_pot 512*512*64]
//
// HMMA implicit GEMM (mma.sync m16n8k16 f16, f32 acc), split-2 fp16 emulation.
// Warp tile 32 px x 32 couts; block = 128 px x 64 couts; 3 CTAs/SM (RF-capped).
// R14: cross-half MMA interleave (RAW distance 8) + warp-staggered tap order.

#define HH 512
#define WW 512
#define CIN 16
#define COUT 64

#define B_BYTES (9 * 2 * 2 * 2 * 32 * 16) /* 36864 */
#define A_PITCH 48                     /* bytes per pixel-row: 16 ci f16 + pad */
#define A_BUF   (130 * A_PITCH)        /* 6240 per (split,row) buffer */
#define A_OFF   B_BYTES
#define SMEM_TOTAL (A_OFF + 6 * A_BUF) /* 74304 ; x3 CTAs = 222912 <= 228KB */

// B fragments: [tap][cbhalf][split][ntpair][lane]{16B = 2 frags}
__device__ static uint2 g_Bfrag[9 * 2 * 2 * 2 * 32 * 2];

__device__ __forceinline__ uint32_t smem_u32(const void* p) {
    uint32_t a;
    asm("{ .reg .u64 t; cvta.to.shared.u64 t, %1; cvt.u32.u64 %0, t; }"
        : "=r"(a) : "l"(p));
    return a;
}
__device__ __forceinline__ uint32_t pack_h2(float a, float b) {
    __half2 h = __floats2half2_rn(a, b);
    return *(uint32_t*)&h;
}
__device__ __forceinline__ float h_rt(float v) {
    return __half2float(__float2half_rn(v));
}
__device__ __forceinline__ void ldmatrix_x4(uint32_t* r, uint32_t addr) {
    asm volatile("ldmatrix.sync.aligned.m8n8.x4.shared.b16 {%0,%1,%2,%3}, [%4];"
                 : "=r"(r[0]), "=r"(r[1]), "=r"(r[2]), "=r"(r[3]) : "r"(addr));
}
__device__ __forceinline__ void mma_f16(float* d, const uint32_t* a, uint2 b) {
    asm volatile(
        "mma.sync.aligned.m16n8k16.row.col.f32.f16.f16.f32 "
        "{%0,%1,%2,%3}, {%4,%5,%6,%7}, {%8,%9}, {%0,%1,%2,%3};"
        : "+f"(d[0]), "+f"(d[1]), "+f"(d[2]), "+f"(d[3])
        : "r"(a[0]), "r"(a[1]), "r"(a[2]), "r"(a[3]), "r"(b.x), "r"(b.y));
}
__device__ __forceinline__ void cp_async16(uint32_t dst, const void* src) {
    asm volatile("cp.async.cg.shared.global [%0], [%1], 16;"
                 :: "r"(dst), "l"(src) : "memory");
}

// ---- prep: B fragments (hi/lo) in m16n8k16 .col layout, LDS.128-friendly ----
__global__ void prep_weights(const float* __restrict__ wt) {
    int idx = blockIdx.x * 256 + threadIdx.x;   // one uint2 each; 4608 total
    if (idx >= 9 * 2 * 2 * 2 * 32 * 2) return;
    int ni   = idx & 1;
    int lane = (idx >> 1) & 31;
    int np   = (idx >> 6) & 1;
    int s    = (idx >> 7) & 1;
    int cbh  = (idx >> 8) & 1;
    int tap  = idx >> 9;
    int nt = cbh * 4 + np * 2 + ni;       // global n-tile 0..7
    int g = lane >> 2, tg = lane & 3;
    int n = nt * 8 + g;
    float w[4];
    int kk[4] = {tg * 2, tg * 2 + 1, tg * 2 + 8, tg * 2 + 9};
    #pragma unroll
    for (int j = 0; j < 4; j++) {
        float wv = wt[(tap * 16 + kk[j]) * 64 + n];
        w[j] = s == 0 ? wv : (wv - h_rt(wv));
    }
    g_Bfrag[idx] = make_uint2(pack_h2(w[0], w[1]), pack_h2(w[2], w[3]));
}

// ---- main kernel ----
__global__ void __launch_bounds__(256, 3)
snn_conv_mma(const float* __restrict__ in, const float* __restrict__ oldp,
             float* __restrict__ out_spk, float* __restrict__ out_pot) {
    extern __shared__ char smem[];
    const uint32_t sb = smem_u32(smem);
    const int tid = threadIdx.x;
    const int wid = tid >> 5;
    const int lane = tid & 31;
    const int x0 = blockIdx.x * 128;
    const int y  = blockIdx.y;

    // ---- stage B fragments via cp.async ----
    #pragma unroll
    for (int i = tid; i < B_BYTES / 16; i += 256)
        cp_async16(sb + i * 16, (const char*)g_Bfrag + i * 16);
    asm volatile("cp.async.commit_group;" ::: "memory");

    // ---- stage A: 3 source rows x 130 px x 16 ci, split hi/lo fp16 ----
    for (int i = tid; i < 3 * 130 * 4; i += 256) {
        int q = i & 3;
        int t = i >> 2;
        int p = t % 130;          // buffer row (gx = x0 + p - 1)
        int r = t / 130;          // source row (gy = y + r - 1)
        int gx = x0 + p - 1, gy = y + r - 1;
        float4 v = make_float4(0.f, 0.f, 0.f, 0.f);
        if ((unsigned)gx < WW && (unsigned)gy < HH)
            v = *(const float4*)(in + (gy * WW + gx) * CIN + q * 4);
        float hx = h_rt(v.x), hy = h_rt(v.y);
        float hz = h_rt(v.z), hw = h_rt(v.w);
        char* rh = smem + A_OFF + r * A_BUF + p * A_PITCH + q * 8;
        char* rl = rh + 3 * A_BUF;
        *(uint32_t*)(rh)     = pack_h2(v.x, v.y);
        *(uint32_t*)(rh + 4) = pack_h2(v.z, v.w);
        *(uint32_t*)(rl)     = pack_h2(v.x - hx, v.y - hy);
        *(uint32_t*)(rl + 4) = pack_h2(v.z - hz, v.w - hw);
    }
    asm volatile("cp.async.wait_all;" ::: "memory");
    __syncthreads();

    // warp tile: pixels m0..m0+31, couts cb..cb+31
    const int m0 = (wid >> 1) * 32;
    const int cbh = wid & 1;
    const uint32_t rowsel = (lane & 7) + ((lane >> 3) & 1) * 8;
    const uint32_t koff = (lane >> 4) * 16;

    float acc[2][4][4];    // [px-half][n-tile][frag]
    #pragma unroll
    for (int t = 0; t < 2; t++)
        #pragma unroll
        for (int nt = 0; nt < 4; nt++)
            #pragma unroll
            for (int j = 0; j < 4; j++) acc[t][nt][j] = 0.f;

    #pragma unroll
    for (int tt = 0; tt < 9; tt++) {
        int tap = tt + wid;                   // warp-staggered tap order
        if (tap >= 9) tap -= 9;
        const int dy = tap / 3, dx = tap - dy * 3;

        // ALL loads of this tap first (max MLP)
        const char* bb = smem + (tap * 2 + cbh) * 2048 + lane * 16;
        uint4 h01 = *(const uint4*)(bb);
        uint4 h23 = *(const uint4*)(bb + 512);
        uint4 l01 = *(const uint4*)(bb + 1024);
        uint4 l23 = *(const uint4*)(bb + 1536);

        uint32_t abase = sb + A_OFF + dy * A_BUF +
                         (m0 + dx + rowsel) * A_PITCH + koff;
        uint32_t ah0[4], ah1[4], al0[4], al1[4];
        ldmatrix_x4(ah0, abase);
        ldmatrix_x4(al0, abase + 3 * A_BUF);
        ldmatrix_x4(ah1, abase + 16 * A_PITCH);
        ldmatrix_x4(al1, abase + 3 * A_BUF + 16 * A_PITCH);

        uint2 bh[4] = {make_uint2(h01.x, h01.y), make_uint2(h01.z, h01.w),
                       make_uint2(h23.x, h23.y), make_uint2(h23.z, h23.w)};
        uint2 bl[4] = {make_uint2(l01.x, l01.y), make_uint2(l01.z, l01.w),
                       make_uint2(l23.x, l23.y), make_uint2(l23.z, l23.w)};

        // product-major, cross-half interleave: same-acc RAW distance = 8
        #pragma unroll
        for (int nt = 0; nt < 4; nt++) mma_f16(acc[0][nt], ah0, bh[nt]);
        #pragma unroll
        for (int nt = 0; nt < 4; nt++) mma_f16(acc[1][nt], ah1, bh[nt]);
        #pragma unroll
        for (int nt = 0; nt < 4; nt++) mma_f16(acc[0][nt], ah0, bl[nt]);
        #pragma unroll
        for (int nt = 0; nt < 4; nt++) mma_f16(acc[1][nt], ah1, bl[nt]);
        #pragma unroll
        for (int nt = 0; nt < 4; nt++) mma_f16(acc[0][nt], al0, bh[nt]);
        #pragma unroll
        for (int nt = 0; nt < 4; nt++) mma_f16(acc[1][nt], al1, bh[nt]);
    }

    // ---- epilogue: batched loads per px-half, threshold, streaming stores ----
    const int g = lane >> 2, tg = lane & 3;
    const int cb = cbh * 32;
    #pragma unroll
    for (int t = 0; t < 2; t++) {
        int base0 = (y * WW + x0 + m0 + t * 16 + g) * COUT + cb + tg * 2;
        int base1 = base0 + 8 * COUT;   // second 8-row half
        float2 o[8];
        #pragma unroll
        for (int nt = 0; nt < 4; nt++) {
            o[nt]     = __ldcs((const float2*)(oldp + base0 + nt * 8));
            o[nt + 4] = __ldcs((const float2*)(oldp + base1 + nt * 8));
        }
        #pragma unroll
        for (int half = 0; half < 2; half++) {
            int base = half ? base1 : base0;
            #pragma unroll
            for (int nt = 0; nt < 4; nt++) {
                float2 ov = o[half * 4 + nt];
                float v0 = acc[t][nt][half * 2 + 0] + ov.x;
                float v1 = acc[t][nt][half * 2 + 1] + ov.y;
                bool f0 = v0 >= 1.f, f1 = v1 >= 1.f;
                __stcs((float2*)(out_spk + base + nt * 8),
                       make_float2(f0 ? 1.f : 0.f, f1 ? 1.f : 0.f));
                __stcs((float2*)(out_pot + base + nt * 8),
                       make_float2(f0 ? 0.f : v0, f1 ? 0.f : v1));
            }
        }
    }
}

extern "C" void kernel_launch(void* const* d_in, const int* in_sizes, int n_in,
                              void* d_out, int out_size) {
    const float* in   = (const float*)d_in[0];   // [1,512,512,16]
    const float* wt   = (const float*)d_in[1];   // [3,3,16,64]
    const float* oldp = (const float*)d_in[2];   // [1,512,512,64]
    float* spk = (float*)d_out;
    float* pot = (float*)d_out + in_sizes[2];

    prep_weights<<<(9 * 2 * 2 * 2 * 32 * 2 + 255) / 256, 256>>>(wt);

    cudaFuncSetAttribute(snn_conv_mma,
                         cudaFuncAttributeMaxDynamicSharedMemorySize, SMEM_TOTAL);
    dim3 grid(WW / 128, HH);   // 4 x 512
    snn_conv_mma<<<grid, 256, SMEM_TOTAL>>>(in, oldp, spk, pot);
}